// round 14
// baseline (speedup 1.0000x reference)
#include <cuda_runtime.h>
#include <math.h>

#define BS    32
#define OBJ   128
#define DD    256
#define RR    32
#define EE    64
#define DEPTH 3
#define MTOT  (BS*OBJ)   // 4096

// ---------------- scratch (static device arrays; no allocation) ----------------
__device__ __align__(16) float g_Ao[BS*OBJ*OBJ];      // 2 MB
__device__ __align__(16) float g_Ar[MTOT*RR];         // 0.5MB
__device__ __align__(16) float g_As[MTOT];
__device__ __align__(16) float g_RelW[DEPTH*RR*DD];
__device__ __align__(16) float g_h1[2][MTOT*DD];      // split-K partials (x@W1 [+b1 in part0])
__device__ __align__(16) float g_Xw[2][MTOT*DD];      // split-K partials (x@W2x)
__device__ __align__(16) float g_xb0[MTOT*DD];        // ping
__device__ __align__(16) float g_xb1[MTOT*DD];        // pong

// ---------------- f32x2 packed-FMA helpers ----------------
__device__ __forceinline__ unsigned long long pack2(float lo, float hi) {
    unsigned long long r;
    asm("mov.b64 %0, {%1, %2};" : "=l"(r) : "f"(lo), "f"(hi));
    return r;
}
__device__ __forceinline__ float2 unpack2(unsigned long long v) {
    float2 r;
    asm("mov.b64 {%0, %1}, %2;" : "=f"(r.x), "=f"(r.y) : "l"(v));
    return r;
}
__device__ __forceinline__ void ffma2(unsigned long long& c, unsigned long long a, unsigned long long b) {
    asm("fma.rn.f32x2 %0, %1, %2, %0;" : "+l"(c) : "l"(a), "l"(b));
}

// ---------------- pre: A reduction (blocks 0..4095) + RelW (blocks 4096..4191) ----
__global__ __launch_bounds__(256) void pre_kernel(const float* __restrict__ A,
                                                  const float* __restrict__ rel,
                                                  const float* __restrict__ W2) {
    __shared__ float s[OBJ*RR];              // 16 KB
    int bid = blockIdx.x;
    int t = threadIdx.x;
    if (bid < MTOT) {
        const float4* a4 = (const float4*)(A + (size_t)bid * (OBJ*RR));
        float4* s4 = (float4*)s;
#pragma unroll
        for (int i = 0; i < 4; i++) s4[t + i*256] = a4[t + i*256];
        __syncthreads();
        if (t < OBJ) {
            float sum = 0.f;
            int base = t * RR;
#pragma unroll
            for (int j = 0; j < RR; j++) sum += s[base + ((j + t) & 31)];
            g_Ao[(size_t)bid*OBJ + t] = sum;
        } else if (t < OBJ + RR) {           // one full warp
            int j = t - OBJ;
            float sum = 0.f;
#pragma unroll 16
            for (int o = 0; o < OBJ; o++) sum += s[o*RR + j];
            g_Ar[(size_t)bid*RR + j] = sum;
            float tot = sum;
#pragma unroll
            for (int off = 16; off > 0; off >>= 1) tot += __shfl_down_sync(0xffffffffu, tot, off);
            if (j == 0) g_As[bid] = tot;
        }
    } else {
        int p = bid - MTOT;                  // 0..95
        int dep = p >> 5, r = p & 31, f = t; // 256 threads = 256 output cols
        const float* w  = W2 + (size_t)dep*(DD+EE)*DD + (size_t)DD*DD + f;
        const float* rr = rel + r*EE;
        float acc = 0.f;
#pragma unroll 8
        for (int e = 0; e < EE; e++) acc += rr[e] * w[(size_t)e*DD];
        g_RelW[(size_t)dep*RR*DD + r*DD + f] = acc;
    }
}

// ---------------- GEMM1 (split-K): C[4096,512] = x @ [W1 | W2x] --------------
// BM=128, BN=64, BK=16, 256 threads, 8x4 per thread via f32x2; grid (8, 32, 2)
__global__ __launch_bounds__(256) void gemm1_kernel(
    const float* __restrict__ x0, int insel,
    const float* __restrict__ W1, const float* __restrict__ b1,
    const float* __restrict__ W2, int dep)
{
    const float* xin = (insel == 0) ? x0 : ((insel == 1) ? g_xb0 : g_xb1);
    __shared__ __align__(16) float sA[16][132];   // k-major, stride 132 (16B-aligned rows)
    __shared__ __align__(16) float sB[16][64];

    int bx = blockIdx.x, by = blockIdx.y, kz = blockIdx.z;
    int tid = threadIdx.x;
    int tx = tid & 15, ty = tid >> 4;
    int arow = tid >> 2, akv = tid & 3;
    int brow = tid >> 4, bcol = (tid & 15) * 4;

    const float* Bbase; int ncol;
    if (bx < 4) { Bbase = W1 + (size_t)dep*DD*DD;      ncol = bx*64; }
    else        { Bbase = W2 + (size_t)dep*(DD+EE)*DD; ncol = (bx-4)*64; }

    const float* Ablk = xin + (size_t)(by * 128) * DD + kz * 128;
    const float* Bblk = Bbase + (size_t)(kz * 128) * DD + ncol;

    unsigned long long c2[4][4];
#pragma unroll
    for (int p = 0; p < 4; p++)
#pragma unroll
        for (int j = 0; j < 4; j++) c2[p][j] = 0ull;

    // prefetch tile 0 into registers
    float4 ra0 = *(const float4*)(Ablk + (size_t)arow*DD      + akv*4);
    float4 ra1 = *(const float4*)(Ablk + (size_t)(arow+64)*DD + akv*4);
    float4 rb  = *(const float4*)(Bblk + (size_t)brow*DD      + bcol);

    for (int kt = 0; kt < 8; kt++) {
        sA[akv*4+0][arow] = ra0.x; sA[akv*4+1][arow] = ra0.y;
        sA[akv*4+2][arow] = ra0.z; sA[akv*4+3][arow] = ra0.w;
        sA[akv*4+0][arow+64] = ra1.x; sA[akv*4+1][arow+64] = ra1.y;
        sA[akv*4+2][arow+64] = ra1.z; sA[akv*4+3][arow+64] = ra1.w;
        *(float4*)&sB[brow][bcol] = rb;
        __syncthreads();

        if (kt < 7) {   // prefetch next tile (overlaps compute below)
            const float* Ap = Ablk + (kt+1)*16;
            ra0 = *(const float4*)(Ap + (size_t)arow*DD      + akv*4);
            ra1 = *(const float4*)(Ap + (size_t)(arow+64)*DD + akv*4);
            rb  = *(const float4*)(Bblk + (size_t)((kt+1)*16 + brow)*DD + bcol);
        }

#pragma unroll
        for (int k = 0; k < 16; k++) {
            const unsigned long long* ar = (const unsigned long long*)&sA[k][ty*8];
            unsigned long long a2[4];
#pragma unroll
            for (int p = 0; p < 4; p++) a2[p] = ar[p];
            float4 bv = *(const float4*)&sB[k][tx*4];
            unsigned long long bd0 = pack2(bv.x, bv.x), bd1 = pack2(bv.y, bv.y);
            unsigned long long bd2 = pack2(bv.z, bv.z), bd3 = pack2(bv.w, bv.w);
#pragma unroll
            for (int p = 0; p < 4; p++) {
                ffma2(c2[p][0], a2[p], bd0);
                ffma2(c2[p][1], a2[p], bd1);
                ffma2(c2[p][2], a2[p], bd2);
                ffma2(c2[p][3], a2[p], bd3);
            }
        }
        __syncthreads();
    }

    int nloc = tx * 4;
    if (bx < 4) {
        int n = bx*64 + nloc;
        float4 bias = (kz == 0) ? *(const float4*)(b1 + dep*DD + n) : make_float4(0.f,0.f,0.f,0.f);
        float* h1o = g_h1[kz];
#pragma unroll
        for (int p = 0; p < 4; p++) {
            float2 u0 = unpack2(c2[p][0]), u1 = unpack2(c2[p][1]);
            float2 u2 = unpack2(c2[p][2]), u3 = unpack2(c2[p][3]);
            int m = by*128 + ty*8 + p*2;
            *(float4*)&h1o[(size_t)m*DD + n]     = make_float4(u0.x+bias.x, u1.x+bias.y, u2.x+bias.z, u3.x+bias.w);
            *(float4*)&h1o[(size_t)(m+1)*DD + n] = make_float4(u0.y+bias.x, u1.y+bias.y, u2.y+bias.z, u3.y+bias.w);
        }
    } else {
        int n = (bx-4)*64 + nloc;
        float* xwo = g_Xw[kz];
#pragma unroll
        for (int p = 0; p < 4; p++) {
            float2 u0 = unpack2(c2[p][0]), u1 = unpack2(c2[p][1]);
            float2 u2 = unpack2(c2[p][2]), u3 = unpack2(c2[p][3]);
            int m = by*128 + ty*8 + p*2;
            *(float4*)&xwo[(size_t)m*DD + n]     = make_float4(u0.x, u1.x, u2.x, u3.x);
            *(float4*)&xwo[(size_t)(m+1)*DD + n] = make_float4(u0.y, u1.y, u2.y, u3.y);
        }
    }
}

// ------- combine: out = tanh(h1 + [Ao|Ar]@[Xw|RelW] + As*b2 + x), K=160 -------
// BM=64, BN=64, BK=16, 256 threads, 4x4 per thread; grid (4, 32, 2)
__global__ __launch_bounds__(256) void combine_kernel(
    const float* __restrict__ x0, int insel, int outsel,
    float* __restrict__ out0, const float* __restrict__ b2v, int dep)
{
    const float* xin  = (insel  == 0) ? x0   : ((insel  == 1) ? g_xb0 : g_xb1);
    float*       xout = (outsel == 0) ? out0 : ((outsel == 1) ? g_xb0 : g_xb1);

    __shared__ __align__(16) float sA[16][68];
    __shared__ __align__(16) float sB[16][64];

    int bx = blockIdx.x, b = blockIdx.y, mh = blockIdx.z;
    int tid = threadIdx.x;
    int tx = tid & 15, ty = tid >> 4;          // 16x16 threads -> 64x64 tile (4x4 each)
    int arow = tid >> 2, akv = tid & 3;        // A loader: 64 rows x 16 k = 1 float4/thread
    int brow = tid >> 4, bcol = (tid & 15)*4;  // B loader: 16 rows x 64 = 1 float4/thread
    int n = bx*64 + tx*4;

    const float* Aob = g_Ao + (size_t)(b*OBJ + mh*64) * OBJ;
    const float* Arb = g_Ar + (size_t)(b*OBJ + mh*64) * RR;
    const float* Xw0 = g_Xw[0] + (size_t)(b*OBJ)*DD + bx*64;
    const float* Xw1 = g_Xw[1] + (size_t)(b*OBJ)*DD + bx*64;
    const float* Rw  = g_RelW + (size_t)dep*RR*DD + bx*64;

    unsigned long long c2[2][4];
#pragma unroll
    for (int p = 0; p < 2; p++)
#pragma unroll
        for (int j = 0; j < 4; j++) c2[p][j] = 0ull;

    // prefetch tile 0 (Ao region)
    float4 ra = *(const float4*)(Aob + (size_t)arow*OBJ + akv*4);
    float4 rb;
    {
        float4 t0 = *(const float4*)(Xw0 + (size_t)brow*DD + bcol);
        float4 t1 = *(const float4*)(Xw1 + (size_t)brow*DD + bcol);
        rb = make_float4(t0.x+t1.x, t0.y+t1.y, t0.z+t1.z, t0.w+t1.w);
    }

    for (int kt = 0; kt < 10; kt++) {          // K = 160 = 128 (Ao@Xw) + 32 (Ar@RelW)
        sA[akv*4+0][arow] = ra.x; sA[akv*4+1][arow] = ra.y;
        sA[akv*4+2][arow] = ra.z; sA[akv*4+3][arow] = ra.w;
        *(float4*)&sB[brow][bcol] = rb;
        __syncthreads();

        if (kt < 9) {
            int k0 = (kt+1)*16;
            if (k0 < 128) {
                ra = *(const float4*)(Aob + (size_t)arow*OBJ + k0 + akv*4);
                float4 t0 = *(const float4*)(Xw0 + (size_t)(k0+brow)*DD + bcol);
                float4 t1 = *(const float4*)(Xw1 + (size_t)(k0+brow)*DD + bcol);
                rb = make_float4(t0.x+t1.x, t0.y+t1.y, t0.z+t1.z, t0.w+t1.w);
            } else {
                ra = *(const float4*)(Arb + (size_t)arow*RR + (k0-128) + akv*4);
                rb = *(const float4*)(Rw + (size_t)(k0-128+brow)*DD + bcol);
            }
        }

#pragma unroll
        for (int k = 0; k < 16; k++) {
            const unsigned long long* ar = (const unsigned long long*)&sA[k][ty*4];
            unsigned long long a20 = ar[0], a21 = ar[1];
            float4 bv = *(const float4*)&sB[k][tx*4];
            unsigned long long bd0 = pack2(bv.x, bv.x), bd1 = pack2(bv.y, bv.y);
            unsigned long long bd2 = pack2(bv.z, bv.z), bd3 = pack2(bv.w, bv.w);
            ffma2(c2[0][0], a20, bd0); ffma2(c2[0][1], a20, bd1);
            ffma2(c2[0][2], a20, bd2); ffma2(c2[0][3], a20, bd3);
            ffma2(c2[1][0], a21, bd0); ffma2(c2[1][1], a21, bd1);
            ffma2(c2[1][2], a21, bd2); ffma2(c2[1][3], a21, bd3);
        }
        __syncthreads();
    }

    // epilogue: + (h1a+h1b) + x + As*b2, tanh
    float4 bv2 = *(const float4*)(b2v + dep*DD + n);
    int rowbase = b*OBJ + mh*64;
#pragma unroll
    for (int p = 0; p < 2; p++) {
        float2 u0 = unpack2(c2[p][0]), u1 = unpack2(c2[p][1]);
        float2 u2 = unpack2(c2[p][2]), u3 = unpack2(c2[p][3]);
        int m0 = ty*4 + p*2;
#pragma unroll
        for (int rr2 = 0; rr2 < 2; rr2++) {
            int mm = m0 + rr2;
            size_t idx = (size_t)(rowbase + mm)*DD + n;
            float as = g_As[rowbase + mm];
            float4 ha = *(const float4*)&g_h1[0][idx];
            float4 hb = *(const float4*)&g_h1[1][idx];
            float4 xv = *(const float4*)(xin + idx);
            float c0 = rr2 ? u0.y : u0.x, c1 = rr2 ? u1.y : u1.x;
            float cc2 = rr2 ? u2.y : u2.x, c3 = rr2 ? u3.y : u3.x;
            float4 v;
            v.x = tanhf(c0  + ha.x + hb.x + xv.x + as*bv2.x);
            v.y = tanhf(c1  + ha.y + hb.y + xv.y + as*bv2.y);
            v.z = tanhf(cc2 + ha.z + hb.z + xv.z + as*bv2.z);
            v.w = tanhf(c3  + ha.w + hb.w + xv.w + as*bv2.w);
            *(float4*)(xout + idx) = v;
        }
    }
}

// ---------------- launch ----------------
extern "C" void kernel_launch(void* const* d_in, const int* in_sizes, int n_in,
                              void* d_out, int out_size) {
    const float* x   = (const float*)d_in[0];
    const float* A   = (const float*)d_in[1];
    const float* rel = (const float*)d_in[2];
    const float* W1  = (const float*)d_in[3];
    const float* b1  = (const float*)d_in[4];
    const float* W2  = (const float*)d_in[5];
    const float* b2  = (const float*)d_in[6];
    float* out = (float*)d_out;

    pre_kernel<<<MTOT + RR*DEPTH, 256>>>(A, rel, W2);

    for (int dep = 0; dep < DEPTH; dep++) {
        int insel  = dep;                              // 0 -> x param, 1 -> g_xb0, 2 -> g_xb1
        int outsel = (dep == DEPTH-1) ? 0 : dep + 1;   // last depth writes d_out
        gemm1_kernel<<<dim3(8, 32, 2), 256>>>(x, insel, W1, b1, W2, dep);
        combine_kernel<<<dim3(4, 32, 2), 256>>>(x, insel, outsel, out, b2, dep);
    }
}

// round 15
// speedup vs baseline: 1.0753x; 1.0753x over previous
#include <cuda_runtime.h>
#include <math.h>

#define BS    32
#define OBJ   128
#define DD    256
#define RR    32
#define EE    64
#define DEPTH 3
#define MTOT  (BS*OBJ)   // 4096

// ---------------- scratch (static device arrays; no allocation) ----------------
__device__ __align__(16) float g_Ao[BS*OBJ*OBJ];      // 2 MB
__device__ __align__(16) float g_Ar[MTOT*RR];         // 0.5MB
__device__ __align__(16) float g_As[MTOT];
__device__ __align__(16) float g_RelW[DEPTH*RR*DD];
__device__ __align__(16) float g_h1[2][MTOT*DD];      // split-K partials (x@W1 [+b1 in part0])
__device__ __align__(16) float g_Xw[2][MTOT*DD];      // split-K partials (x@W2x)
__device__ __align__(16) float g_xb0[MTOT*DD];        // ping
__device__ __align__(16) float g_xb1[MTOT*DD];        // pong

// ---------------- f32x2 packed-FMA helpers ----------------
__device__ __forceinline__ unsigned long long pack2(float lo, float hi) {
    unsigned long long r;
    asm("mov.b64 %0, {%1, %2};" : "=l"(r) : "f"(lo), "f"(hi));
    return r;
}
__device__ __forceinline__ float2 unpack2(unsigned long long v) {
    float2 r;
    asm("mov.b64 {%0, %1}, %2;" : "=f"(r.x), "=f"(r.y) : "l"(v));
    return r;
}
__device__ __forceinline__ void ffma2(unsigned long long& c, unsigned long long a, unsigned long long b) {
    asm("fma.rn.f32x2 %0, %1, %2, %0;" : "+l"(c) : "l"(a), "l"(b));
}

// ---------------- pre: A reduction (blocks 0..4095) + RelW (blocks 4096..4191) ----
__global__ __launch_bounds__(256) void pre_kernel(const float* __restrict__ A,
                                                  const float* __restrict__ rel,
                                                  const float* __restrict__ W2) {
    __shared__ float s[OBJ*RR];              // 16 KB
    int bid = blockIdx.x;
    int t = threadIdx.x;
    if (bid < MTOT) {
        const float4* a4 = (const float4*)(A + (size_t)bid * (OBJ*RR));
        float4* s4 = (float4*)s;
#pragma unroll
        for (int i = 0; i < 4; i++) s4[t + i*256] = a4[t + i*256];
        __syncthreads();
        if (t < OBJ) {
            float sum = 0.f;
            int base = t * RR;
#pragma unroll
            for (int j = 0; j < RR; j++) sum += s[base + ((j + t) & 31)];
            g_Ao[(size_t)bid*OBJ + t] = sum;
        } else if (t < OBJ + RR) {           // one full warp
            int j = t - OBJ;
            float sum = 0.f;
#pragma unroll 16
            for (int o = 0; o < OBJ; o++) sum += s[o*RR + j];
            g_Ar[(size_t)bid*RR + j] = sum;
            float tot = sum;
#pragma unroll
            for (int off = 16; off > 0; off >>= 1) tot += __shfl_down_sync(0xffffffffu, tot, off);
            if (j == 0) g_As[bid] = tot;
        }
    } else {
        int p = bid - MTOT;                  // 0..95
        int dep = p >> 5, r = p & 31, f = t; // 256 threads = 256 output cols
        const float* w  = W2 + (size_t)dep*(DD+EE)*DD + (size_t)DD*DD + f;
        const float* rr = rel + r*EE;
        float acc = 0.f;
#pragma unroll 8
        for (int e = 0; e < EE; e++) acc += rr[e] * w[(size_t)e*DD];
        g_RelW[(size_t)dep*RR*DD + r*DD + f] = acc;
    }
}

// ---------------- GEMM1 (split-K): C[4096,512] = x @ [W1 | W2x] --------------
// BM=128, BN=64, BK=16, 256 threads, 8x4 per thread via f32x2; grid (8, 32, 2)
__global__ __launch_bounds__(256) void gemm1_kernel(
    const float* __restrict__ x0, int insel,
    const float* __restrict__ W1, const float* __restrict__ b1,
    const float* __restrict__ W2, int dep)
{
    const float* xin = (insel == 0) ? x0 : ((insel == 1) ? g_xb0 : g_xb1);
    __shared__ __align__(16) float sA[16][132];   // k-major, stride 132 (16B-aligned rows)
    __shared__ __align__(16) float sB[16][64];

    int bx = blockIdx.x, by = blockIdx.y, kz = blockIdx.z;
    int tid = threadIdx.x;
    int tx = tid & 15, ty = tid >> 4;
    int arow = tid >> 2, akv = tid & 3;
    int brow = tid >> 4, bcol = (tid & 15) * 4;

    const float* Bbase; int ncol;
    if (bx < 4) { Bbase = W1 + (size_t)dep*DD*DD;      ncol = bx*64; }
    else        { Bbase = W2 + (size_t)dep*(DD+EE)*DD; ncol = (bx-4)*64; }

    const float* Ablk = xin + (size_t)(by * 128) * DD + kz * 128;
    const float* Bblk = Bbase + (size_t)(kz * 128) * DD + ncol;

    unsigned long long c2[4][4];
#pragma unroll
    for (int p = 0; p < 4; p++)
#pragma unroll
        for (int j = 0; j < 4; j++) c2[p][j] = 0ull;

    // prefetch tile 0 into registers
    float4 ra0 = *(const float4*)(Ablk + (size_t)arow*DD      + akv*4);
    float4 ra1 = *(const float4*)(Ablk + (size_t)(arow+64)*DD + akv*4);
    float4 rb  = *(const float4*)(Bblk + (size_t)brow*DD      + bcol);

    for (int kt = 0; kt < 8; kt++) {
        sA[akv*4+0][arow] = ra0.x; sA[akv*4+1][arow] = ra0.y;
        sA[akv*4+2][arow] = ra0.z; sA[akv*4+3][arow] = ra0.w;
        sA[akv*4+0][arow+64] = ra1.x; sA[akv*4+1][arow+64] = ra1.y;
        sA[akv*4+2][arow+64] = ra1.z; sA[akv*4+3][arow+64] = ra1.w;
        *(float4*)&sB[brow][bcol] = rb;
        __syncthreads();

        if (kt < 7) {   // prefetch next tile (overlaps compute below)
            const float* Ap = Ablk + (kt+1)*16;
            ra0 = *(const float4*)(Ap + (size_t)arow*DD      + akv*4);
            ra1 = *(const float4*)(Ap + (size_t)(arow+64)*DD + akv*4);
            rb  = *(const float4*)(Bblk + (size_t)((kt+1)*16 + brow)*DD + bcol);
        }

#pragma unroll
        for (int k = 0; k < 16; k++) {
            const unsigned long long* ar = (const unsigned long long*)&sA[k][ty*8];
            unsigned long long a2[4];
#pragma unroll
            for (int p = 0; p < 4; p++) a2[p] = ar[p];
            float4 bv = *(const float4*)&sB[k][tx*4];
            unsigned long long bd0 = pack2(bv.x, bv.x), bd1 = pack2(bv.y, bv.y);
            unsigned long long bd2 = pack2(bv.z, bv.z), bd3 = pack2(bv.w, bv.w);
#pragma unroll
            for (int p = 0; p < 4; p++) {
                ffma2(c2[p][0], a2[p], bd0);
                ffma2(c2[p][1], a2[p], bd1);
                ffma2(c2[p][2], a2[p], bd2);
                ffma2(c2[p][3], a2[p], bd3);
            }
        }
        __syncthreads();
    }

    int nloc = tx * 4;
    if (bx < 4) {
        int n = bx*64 + nloc;
        float4 bias = (kz == 0) ? *(const float4*)(b1 + dep*DD + n) : make_float4(0.f,0.f,0.f,0.f);
        float* h1o = g_h1[kz];
#pragma unroll
        for (int p = 0; p < 4; p++) {
            float2 u0 = unpack2(c2[p][0]), u1 = unpack2(c2[p][1]);
            float2 u2 = unpack2(c2[p][2]), u3 = unpack2(c2[p][3]);
            int m = by*128 + ty*8 + p*2;
            *(float4*)&h1o[(size_t)m*DD + n]     = make_float4(u0.x+bias.x, u1.x+bias.y, u2.x+bias.z, u3.x+bias.w);
            *(float4*)&h1o[(size_t)(m+1)*DD + n] = make_float4(u0.y+bias.x, u1.y+bias.y, u2.y+bias.z, u3.y+bias.w);
        }
    } else {
        int n = (bx-4)*64 + nloc;
        float* xwo = g_Xw[kz];
#pragma unroll
        for (int p = 0; p < 4; p++) {
            float2 u0 = unpack2(c2[p][0]), u1 = unpack2(c2[p][1]);
            float2 u2 = unpack2(c2[p][2]), u3 = unpack2(c2[p][3]);
            int m = by*128 + ty*8 + p*2;
            *(float4*)&xwo[(size_t)m*DD + n]     = make_float4(u0.x, u1.x, u2.x, u3.x);
            *(float4*)&xwo[(size_t)(m+1)*DD + n] = make_float4(u0.y, u1.y, u2.y, u3.y);
        }
    }
}

// ------- combine: out = tanh(h1 + [Ao|Ar]@[Xw|RelW] + As*b2 + x), K=160 -------
// BM=64, BN=64, BK=16, 256 threads, 4x4 per thread; grid (4, 32, 2)
__global__ __launch_bounds__(256) void combine_kernel(
    const float* __restrict__ x0, int insel, int outsel,
    float* __restrict__ out0, const float* __restrict__ b2v, int dep)
{
    const float* xin  = (insel  == 0) ? x0   : ((insel  == 1) ? g_xb0 : g_xb1);
    float*       xout = (outsel == 0) ? out0 : ((outsel == 1) ? g_xb0 : g_xb1);

    __shared__ __align__(16) float sA[16][68];
    __shared__ __align__(16) float sB[16][64];

    int bx = blockIdx.x, b = blockIdx.y, mh = blockIdx.z;
    int tid = threadIdx.x;
    int tx = tid & 15, ty = tid >> 4;          // 16x16 threads -> 64x64 tile (4x4 each)
    int arow = tid >> 2, akv = tid & 3;        // A loader: 64 rows x 16 k = 1 float4/thread
    int brow = tid >> 4, bcol = (tid & 15)*4;  // B loader: 16 rows x 64 = 1 float4/thread
    int n = bx*64 + tx*4;

    const float* Aob = g_Ao + (size_t)(b*OBJ + mh*64) * OBJ;
    const float* Arb = g_Ar + (size_t)(b*OBJ + mh*64) * RR;
    const float* Xw0 = g_Xw[0] + (size_t)(b*OBJ)*DD + bx*64;
    const float* Xw1 = g_Xw[1] + (size_t)(b*OBJ)*DD + bx*64;
    const float* Rw  = g_RelW + (size_t)dep*RR*DD + bx*64;

    unsigned long long c2[2][4];
#pragma unroll
    for (int p = 0; p < 2; p++)
#pragma unroll
        for (int j = 0; j < 4; j++) c2[p][j] = 0ull;

    // prefetch tile 0 (Ao region)
    float4 ra = *(const float4*)(Aob + (size_t)arow*OBJ + akv*4);
    float4 rb;
    {
        float4 t0 = *(const float4*)(Xw0 + (size_t)brow*DD + bcol);
        float4 t1 = *(const float4*)(Xw1 + (size_t)brow*DD + bcol);
        rb = make_float4(t0.x+t1.x, t0.y+t1.y, t0.z+t1.z, t0.w+t1.w);
    }

    for (int kt = 0; kt < 10; kt++) {          // K = 160 = 128 (Ao@Xw) + 32 (Ar@RelW)
        sA[akv*4+0][arow] = ra.x; sA[akv*4+1][arow] = ra.y;
        sA[akv*4+2][arow] = ra.z; sA[akv*4+3][arow] = ra.w;
        *(float4*)&sB[brow][bcol] = rb;
        __syncthreads();

        if (kt < 9) {
            int k0 = (kt+1)*16;
            if (k0 < 128) {
                ra = *(const float4*)(Aob + (size_t)arow*OBJ + k0 + akv*4);
                float4 t0 = *(const float4*)(Xw0 + (size_t)(k0+brow)*DD + bcol);
                float4 t1 = *(const float4*)(Xw1 + (size_t)(k0+brow)*DD + bcol);
                rb = make_float4(t0.x+t1.x, t0.y+t1.y, t0.z+t1.z, t0.w+t1.w);
            } else {
                ra = *(const float4*)(Arb + (size_t)arow*RR + (k0-128) + akv*4);
                rb = *(const float4*)(Rw + (size_t)(k0-128+brow)*DD + bcol);
            }
        }

#pragma unroll
        for (int k = 0; k < 16; k++) {
            const unsigned long long* ar = (const unsigned long long*)&sA[k][ty*4];
            unsigned long long a20 = ar[0], a21 = ar[1];
            float4 bv = *(const float4*)&sB[k][tx*4];
            unsigned long long bd0 = pack2(bv.x, bv.x), bd1 = pack2(bv.y, bv.y);
            unsigned long long bd2 = pack2(bv.z, bv.z), bd3 = pack2(bv.w, bv.w);
            ffma2(c2[0][0], a20, bd0); ffma2(c2[0][1], a20, bd1);
            ffma2(c2[0][2], a20, bd2); ffma2(c2[0][3], a20, bd3);
            ffma2(c2[1][0], a21, bd0); ffma2(c2[1][1], a21, bd1);
            ffma2(c2[1][2], a21, bd2); ffma2(c2[1][3], a21, bd3);
        }
        __syncthreads();
    }

    // epilogue: + (h1a+h1b) + x + As*b2, tanh
    float4 bv2 = *(const float4*)(b2v + dep*DD + n);
    int rowbase = b*OBJ + mh*64;
#pragma unroll
    for (int p = 0; p < 2; p++) {
        float2 u0 = unpack2(c2[p][0]), u1 = unpack2(c2[p][1]);
        float2 u2 = unpack2(c2[p][2]), u3 = unpack2(c2[p][3]);
        int m0 = ty*4 + p*2;
#pragma unroll
        for (int rr2 = 0; rr2 < 2; rr2++) {
            int mm = m0 + rr2;
            size_t idx = (size_t)(rowbase + mm)*DD + n;
            float as = g_As[rowbase + mm];
            float4 ha = *(const float4*)&g_h1[0][idx];
            float4 hb = *(const float4*)&g_h1[1][idx];
            float4 xv = *(const float4*)(xin + idx);
            float c0 = rr2 ? u0.y : u0.x, c1 = rr2 ? u1.y : u1.x;
            float cc2 = rr2 ? u2.y : u2.x, c3 = rr2 ? u3.y : u3.x;
            float4 v;
            v.x = tanhf(c0  + ha.x + hb.x + xv.x + as*bv2.x);
            v.y = tanhf(c1  + ha.y + hb.y + xv.y + as*bv2.y);
            v.z = tanhf(cc2 + ha.z + hb.z + xv.z + as*bv2.z);
            v.w = tanhf(c3  + ha.w + hb.w + xv.w + as*bv2.w);
            *(float4*)(xout + idx) = v;
        }
    }
}

// ---------------- launch ----------------
extern "C" void kernel_launch(void* const* d_in, const int* in_sizes, int n_in,
                              void* d_out, int out_size) {
    const float* x   = (const float*)d_in[0];
    const float* A   = (const float*)d_in[1];
    const float* rel = (const float*)d_in[2];
    const float* W1  = (const float*)d_in[3];
    const float* b1  = (const float*)d_in[4];
    const float* W2  = (const float*)d_in[5];
    const float* b2  = (const float*)d_in[6];
    float* out = (float*)d_out;

    pre_kernel<<<MTOT + RR*DEPTH, 256>>>(A, rel, W2);

    for (int dep = 0; dep < DEPTH; dep++) {
        int insel  = dep;                              // 0 -> x param, 1 -> g_xb0, 2 -> g_xb1
        int outsel = (dep == DEPTH-1) ? 0 : dep + 1;   // last depth writes d_out
        gemm1_kernel<<<dim3(8, 32, 2), 256>>>(x, insel, W1, b1, W2, dep);
        combine_kernel<<<dim3(4, 32, 2), 256>>>(x, insel, outsel, out, b2, dep);
    }
}